// round 2
// baseline (speedup 1.0000x reference)
#include <cuda_runtime.h>
#include <math.h>

#define NN   100000
#define EE   600000
#define FINN 256
#define HH   128
#define CC   47
#define NOUTT 10000

// ---------------- scratch (device globals; no allocations allowed) ----------
__device__ float g_bufA[(size_t)NN * HH];
__device__ float g_bufB[(size_t)NN * HH];
__device__ float g_bufC[(size_t)NN * HH];
__device__ float g_acc [(size_t)NN * HH * 2];   // interleaved {sum(w), sum(m*w)} per (node,feat)

// ---------------- zero kernel ------------------------------------------------
__global__ void zero_kernel(float4* __restrict__ p, int n4) {
    int i = blockIdx.x * blockDim.x + threadIdx.x;
    if (i < n4) p[i] = make_float4(0.f, 0.f, 0.f, 0.f);
}

// ---------------- edge pass: fused softmax-numerator/denominator ------------
// One warp per edge. Lane l handles features [4l,4l+4).
// m = relu(h[src])+eps ; w = exp(m) ; acc[dst] += {w, m*w} (vector RED)
__global__ void edge_kernel(const float* __restrict__ h,
                            const int*   __restrict__ src,
                            const int*   __restrict__ dst,
                            float*       __restrict__ acc, int E) {
    int gw   = (blockIdx.x * blockDim.x + threadIdx.x) >> 5;
    int lane = threadIdx.x & 31;
    if (gw >= E) return;
    int s = __ldg(src + gw);
    int d = __ldg(dst + gw);
    float4 v = *(const float4*)&h[s * HH + lane * 4];
    float m0 = fmaxf(v.x, 0.f) + 1e-7f;
    float m1 = fmaxf(v.y, 0.f) + 1e-7f;
    float m2 = fmaxf(v.z, 0.f) + 1e-7f;
    float m3 = fmaxf(v.w, 0.f) + 1e-7f;
    float w0 = __expf(m0), w1 = __expf(m1), w2 = __expf(m2), w3 = __expf(m3);
    float* base = acc + d * (2 * HH) + lane * 8;
    asm volatile("red.global.add.v4.f32 [%0], {%1,%2,%3,%4};"
                 :: "l"(base), "f"(w0), "f"(m0 * w0), "f"(w1), "f"(m1 * w1) : "memory");
    asm volatile("red.global.add.v4.f32 [%0], {%1,%2,%3,%4};"
                 :: "l"(base + 4), "f"(w2), "f"(m2 * w2), "f"(w3), "f"(m3 * w3) : "memory");
}

// ---------------- GEMM: C[M,128] = A'[M,K] @ W[K,128] + bias (+resid) -------
// AMODE 0: A' = A (plain, lda = K)
// AMODE 1: A' = agg + A, where agg = acc.mw / (acc.w + 1e-16), lda = 128
constexpr int BM = 64, BN = 128, BK = 16, TM = 4, TN = 8;

template<int AMODE>
__global__ void gemm128_kernel(const float* __restrict__ A, int lda,
                               const float* __restrict__ accb,
                               const float* __restrict__ W,
                               const float* __restrict__ bias,
                               const float* __restrict__ resid,
                               float* __restrict__ C, int M) {
    __shared__ float As[BK][BM + 4];   // +4 keeps 16B row alignment, tames conflicts
    __shared__ float Bs[BK][BN];
    const int tid = threadIdx.x;
    const int tx = tid & 15;   // col group
    const int ty = tid >> 4;   // row group
    const int bm = blockIdx.x * BM;
    const int K = lda;

    float accr[TM][TN];
#pragma unroll
    for (int i = 0; i < TM; i++)
#pragma unroll
        for (int j = 0; j < TN; j++) accr[i][j] = 0.f;

    for (int k0 = 0; k0 < K; k0 += BK) {
        // A tile: BM x BK scalars (coalesced along k)
#pragma unroll
        for (int l = 0; l < (BM * BK) / 256; l++) {
            int idx = tid + l * 256;
            int r = idx >> 4;
            int kk = idx & 15;
            int grow = bm + r;
            float v = 0.f;
            if (grow < M) {
                int k = k0 + kk;
                if (AMODE == 0) {
                    v = A[grow * lda + k];
                } else {
                    float w  = accb[grow * 256 + 2 * k];
                    float mw = accb[grow * 256 + 2 * k + 1];
                    v = mw / (w + 1e-16f) + A[grow * HH + k];
                }
            }
            As[kk][r] = v;
        }
        // B tile: BK x BN via float4
#pragma unroll
        for (int l = 0; l < (BK * BN) / (256 * 4); l++) {
            int idx4 = tid + l * 256;
            int kk = idx4 >> 5;
            int c  = (idx4 & 31) * 4;
            *(float4*)&Bs[kk][c] = *(const float4*)&W[(k0 + kk) * BN + c];
        }
        __syncthreads();
#pragma unroll
        for (int kk = 0; kk < BK; kk++) {
            float rm[TM], rn[TN];
#pragma unroll
            for (int i = 0; i < TM; i++) rm[i] = As[kk][ty * TM + i];
#pragma unroll
            for (int j = 0; j < TN; j++) rn[j] = Bs[kk][tx * TN + j];
#pragma unroll
            for (int i = 0; i < TM; i++)
#pragma unroll
                for (int j = 0; j < TN; j++) accr[i][j] += rm[i] * rn[j];
        }
        __syncthreads();
    }
#pragma unroll
    for (int i = 0; i < TM; i++) {
        int row = bm + ty * TM + i;
        if (row >= M) continue;
#pragma unroll
        for (int j = 0; j < TN; j++) {
            int col = tx * TN + j;
            float v = accr[i][j] + bias[col];
            if (resid) v += resid[row * BN + col];
            C[row * BN + col] = v;
        }
    }
}

// ---------------- LayerNorm + ReLU (warp per row) ---------------------------
__global__ void ln_relu_kernel(const float* __restrict__ in,
                               const float* __restrict__ g,
                               const float* __restrict__ b,
                               float* __restrict__ out, int M) {
    int gw   = (blockIdx.x * blockDim.x + threadIdx.x) >> 5;
    int lane = threadIdx.x & 31;
    if (gw >= M) return;
    float4 v = *(const float4*)&in[gw * HH + lane * 4];
    float s = v.x + v.y + v.z + v.w;
#pragma unroll
    for (int o = 16; o; o >>= 1) s += __shfl_xor_sync(0xffffffffu, s, o);
    float mu = s * (1.f / 128.f);
    float dx = v.x - mu, dy = v.y - mu, dz = v.z - mu, dw = v.w - mu;
    float q = dx * dx + dy * dy + dz * dz + dw * dw;
#pragma unroll
    for (int o = 16; o; o >>= 1) q += __shfl_xor_sync(0xffffffffu, q, o);
    float rs = rsqrtf(q * (1.f / 128.f) + 1e-5f);
    float4 gv = *(const float4*)&g[lane * 4];
    float4 bv = *(const float4*)&b[lane * 4];
    float4 o4;
    o4.x = fmaxf(dx * rs * gv.x + bv.x, 0.f);
    o4.y = fmaxf(dy * rs * gv.y + bv.y, 0.f);
    o4.z = fmaxf(dz * rs * gv.z + bv.z, 0.f);
    o4.w = fmaxf(dw * rs * gv.w + bv.w, 0.f);
    *(float4*)&out[gw * HH + lane * 4] = o4;
}

// ---------------- row gather out[n] = in[map[n]] ----------------------------
__global__ void gather_kernel(const float* __restrict__ in,
                              const int*   __restrict__ map,
                              float*       __restrict__ out, int M) {
    int i = blockIdx.x * blockDim.x + threadIdx.x;
    int n = i >> 5, f = i & 31;
    if (n >= M) return;
    int r = __ldg(map + n);
    ((float4*)out)[n * 32 + f] = ((const float4*)in)[r * 32 + f];
}

// ---------------- final: gather + LN + ReLU + pred GEMV + log_softmax -------
__global__ void final_kernel(const float* __restrict__ h,
                             const int*   __restrict__ fmap,
                             const float* __restrict__ g,
                             const float* __restrict__ b,
                             const float* __restrict__ pw,
                             const float* __restrict__ pb,
                             float* __restrict__ out) {
    __shared__ float sv[128];
    __shared__ float sl[CC];
    __shared__ float red[4];
    __shared__ float stats[2];
    int t = threadIdx.x;
    int lane = t & 31, warp = t >> 5;
    int row = __ldg(fmap + blockIdx.x);
    float x = h[row * HH + t];
    float s = x;
#pragma unroll
    for (int o = 16; o; o >>= 1) s += __shfl_xor_sync(0xffffffffu, s, o);
    if (lane == 0) red[warp] = s;
    __syncthreads();
    float mu = (red[0] + red[1] + red[2] + red[3]) * (1.f / 128.f);
    float d = x - mu;
    float q = d * d;
#pragma unroll
    for (int o = 16; o; o >>= 1) q += __shfl_xor_sync(0xffffffffu, q, o);
    __syncthreads();
    if (lane == 0) red[warp] = q;
    __syncthreads();
    float var = (red[0] + red[1] + red[2] + red[3]) * (1.f / 128.f);
    float rs = rsqrtf(var + 1e-5f);
    sv[t] = fmaxf(d * rs * g[t] + b[t], 0.f);
    __syncthreads();
    if (t < CC) {
        float a = pb[t];
#pragma unroll 8
        for (int k = 0; k < 128; k++) a += sv[k] * pw[k * CC + t];
        sl[t] = a;
    }
    __syncthreads();
    if (t == 0) {
        float mx = -1e30f;
        for (int c = 0; c < CC; c++) mx = fmaxf(mx, sl[c]);
        float se = 0.f;
        for (int c = 0; c < CC; c++) se += expf(sl[c] - mx);
        stats[0] = mx; stats[1] = logf(se);
    }
    __syncthreads();
    if (t < CC) out[blockIdx.x * CC + t] = sl[t] - stats[0] - stats[1];
}

// ---------------- host orchestration ----------------------------------------
extern "C" void kernel_launch(void* const* d_in, const int* in_sizes, int n_in,
                              void* d_out, int out_size) {
    const float* x        = (const float*)d_in[0];
    const int*   src      = (const int*)  d_in[1];
    const int*   dst      = (const int*)  d_in[2];
    const int*   node_map = (const int*)  d_in[3];
    const int*   fmap     = (const int*)  d_in[4];
    const float* enc_w    = (const float*)d_in[5];
    const float* enc_b    = (const float*)d_in[6];
    const float* gcn_w    = (const float*)d_in[7];
    const float* gcn_b    = (const float*)d_in[8];
    const float* ln_g     = (const float*)d_in[9];
    const float* ln_b     = (const float*)d_in[10];
    const float* pred_w   = (const float*)d_in[11];
    const float* pred_b   = (const float*)d_in[12];
    float* out = (float*)d_out;

    float *bA, *bB, *bC, *acc;
    cudaGetSymbolAddress((void**)&bA,  g_bufA);
    cudaGetSymbolAddress((void**)&bB,  g_bufB);
    cudaGetSymbolAddress((void**)&bC,  g_bufC);
    cudaGetSymbolAddress((void**)&acc, g_acc);

    const int gemmGrid = (NN + BM - 1) / BM;
    const int accN4    = NN * HH * 2 / 4;
    const int zeroGrid = (accN4 + 255) / 256;
    const int edgeGrid = (EE * 32 + 255) / 256;
    const int rowGrid  = (NN * 32 + 255) / 256;

    // encoder: h = x @ enc_w + enc_b                       -> bA
    gemm128_kernel<0><<<gemmGrid, 256>>>(x, FINN, nullptr, enc_w, enc_b, nullptr, bA, NN);

    // conv0 (edges block 0): h = (agg(bA)+bA) @ W0 + b0    -> bB
    zero_kernel<<<zeroGrid, 256>>>((float4*)acc, accN4);
    edge_kernel<<<edgeGrid, 256>>>(bA, src, dst, acc, EE);
    gemm128_kernel<1><<<gemmGrid, 256>>>(bA, HH, acc, gcn_w, gcn_b, nullptr, bB, NN);

    // layer 1: h2 = relu(LN(bB)); h = conv(h2, edges0)+bB; h = h[node_map0]
    ln_relu_kernel<<<rowGrid, 256>>>(bB, ln_g, ln_b, bA, NN);
    zero_kernel<<<zeroGrid, 256>>>((float4*)acc, accN4);
    edge_kernel<<<edgeGrid, 256>>>(bA, src, dst, acc, EE);
    gemm128_kernel<1><<<gemmGrid, 256>>>(bA, HH, acc, gcn_w + HH * HH, gcn_b + HH, bB, bC, NN);
    gather_kernel<<<rowGrid, 256>>>(bC, node_map, bA, NN);

    // layer 2: h2 = relu(LN(bA)); h = conv(h2, edges1)+bA; h = h[node_map1]
    ln_relu_kernel<<<rowGrid, 256>>>(bA, ln_g + HH, ln_b + HH, bB, NN);
    zero_kernel<<<zeroGrid, 256>>>((float4*)acc, accN4);
    edge_kernel<<<edgeGrid, 256>>>(bB, src + EE, dst + EE, acc, EE);
    gemm128_kernel<1><<<gemmGrid, 256>>>(bB, HH, acc, gcn_w + 2 * HH * HH, gcn_b + 2 * HH, bA, bC, NN);
    gather_kernel<<<rowGrid, 256>>>(bC, node_map + NN, bB, NN);

    // final: LN+ReLU on the 10k seed rows only, pred linear, log_softmax
    final_kernel<<<NOUTT, 128>>>(bB, fmap, ln_g + 2 * HH, ln_b + 2 * HH, pred_w, pred_b, out);
}

// round 4
// speedup vs baseline: 1.2016x; 1.2016x over previous
#include <cuda_runtime.h>
#include <cuda_bf16.h>
#include <math.h>

#define NN   100000
#define EE   600000
#define FINN 256
#define HH   128
#define CC   47
#define NOUTT 10000

// ---------------- scratch (device globals; no allocations allowed) ----------
__device__ float g_bufA[(size_t)NN * HH];
__device__ float g_bufB[(size_t)NN * HH];
__device__ float g_bufC[(size_t)NN * HH];
__device__ float g_acc [(size_t)NN * HH * 2];   // interleaved {sum(w), sum(m*w)}

// ======================= TF32 mma helpers ===================================
__device__ __forceinline__ unsigned f2tf32(float x) {
    unsigned r;
    asm("cvt.rna.tf32.f32 %0, %1;" : "=r"(r) : "f"(x));
    return r;
}

__device__ __forceinline__ void mma_tf32(float* d, const unsigned* a, const unsigned* b) {
    asm volatile(
        "mma.sync.aligned.m16n8k8.row.col.f32.tf32.tf32.f32 "
        "{%0,%1,%2,%3}, {%4,%5,%6,%7}, {%8,%9}, {%0,%1,%2,%3};"
        : "+f"(d[0]), "+f"(d[1]), "+f"(d[2]), "+f"(d[3])
        : "r"(a[0]), "r"(a[1]), "r"(a[2]), "r"(a[3]), "r"(b[0]), "r"(b[1]));
}

// ---------------- TF32 split GEMM: C[M,128] = A'[M,K] @ W[K,128] + bias -----
// AMODE 0: A' = A (lda = K).  AMODE 1: A' = acc.mw/(acc.w+eps) + A (lda = 128).
// CTA: 256 thr = 8 warps (2x4), tile 128x128, K chunked by 32.
#define APITCH 36
#define BPITCH 136

template<int AMODE>
__global__ __launch_bounds__(256) void gemm_mma_kernel(
    const float* __restrict__ A, int K,
    const float* __restrict__ accb,
    const float* __restrict__ W,
    const float* __restrict__ bias,
    const float* __restrict__ resid,
    float* __restrict__ C, int M)
{
    __shared__ float As[128][APITCH];
    __shared__ float Bs[32][BPITCH];

    const int tid  = threadIdx.x;
    const int wid  = tid >> 5, lane = tid & 31;
    const int wr   = wid >> 2, wc = wid & 3;      // warp 2x4 grid
    const int qid  = lane >> 2, qtr = lane & 3;   // quad row / thread-in-quad
    const int bm   = blockIdx.x * 128;

    // A-tile loader mapping: 2 threads per row, 16 floats each
    const int arow  = tid >> 1;
    const int apart = (tid & 1) * 16;
    const int agrow = bm + arow;
    const bool ain  = agrow < M;
    // B-tile loader mapping: 8 threads per k-row, 16 floats each
    const int brow = tid >> 3;
    const int bcol = (tid & 7) * 16;

    float acc[4][4][4];
#pragma unroll
    for (int i = 0; i < 4; i++)
#pragma unroll
        for (int j = 0; j < 4; j++)
#pragma unroll
            for (int q = 0; q < 4; q++) acc[i][j][q] = 0.f;

    const int nchunks = K >> 5;
    for (int ch = 0; ch < nchunks; ch++) {
        const int k0 = ch * 32;
        // ---- load A tile (with optional agg fusion) ----
        {
            float v[16];
            if (ain) {
                if (AMODE == 0) {
                    const float4* ap = (const float4*)(A + (size_t)agrow * K + k0 + apart);
#pragma unroll
                    for (int j = 0; j < 4; j++) {
                        float4 t = ap[j];
                        v[j * 4 + 0] = t.x; v[j * 4 + 1] = t.y;
                        v[j * 4 + 2] = t.z; v[j * 4 + 3] = t.w;
                    }
                } else {
                    const float4* cp = (const float4*)(accb + (size_t)agrow * 256 + 2 * (k0 + apart));
                    const float4* ap = (const float4*)(A + (size_t)agrow * 128 + k0 + apart);
#pragma unroll
                    for (int j = 0; j < 8; j++) {
                        float4 t = cp[j];
                        v[j * 2 + 0] = t.y / (t.x + 1e-16f);
                        v[j * 2 + 1] = t.w / (t.z + 1e-16f);
                    }
#pragma unroll
                    for (int j = 0; j < 4; j++) {
                        float4 t = ap[j];
                        v[j * 4 + 0] += t.x; v[j * 4 + 1] += t.y;
                        v[j * 4 + 2] += t.z; v[j * 4 + 3] += t.w;
                    }
                }
            } else {
#pragma unroll
                for (int j = 0; j < 16; j++) v[j] = 0.f;
            }
#pragma unroll
            for (int j = 0; j < 4; j++)
                *(float4*)&As[arow][apart + j * 4] =
                    make_float4(v[j * 4], v[j * 4 + 1], v[j * 4 + 2], v[j * 4 + 3]);
        }
        // ---- load B tile ----
        {
            const float4* wp = (const float4*)(W + (size_t)(k0 + brow) * 128 + bcol);
#pragma unroll
            for (int j = 0; j < 4; j++) *(float4*)&Bs[brow][bcol + j * 4] = wp[j];
        }
        __syncthreads();

        // ---- 4 k-steps of 8 ----
#pragma unroll
        for (int ks = 0; ks < 4; ks++) {
            const int kb = ks * 8;
            unsigned ahi[4][4], alo[4][4];
#pragma unroll
            for (int mf = 0; mf < 4; mf++) {
                int r0 = wr * 64 + mf * 16 + qid;
                float x0 = As[r0][kb + qtr];
                float x1 = As[r0 + 8][kb + qtr];
                float x2 = As[r0][kb + qtr + 4];
                float x3 = As[r0 + 8][kb + qtr + 4];
                ahi[mf][0] = f2tf32(x0); alo[mf][0] = f2tf32(x0 - __uint_as_float(ahi[mf][0]));
                ahi[mf][1] = f2tf32(x1); alo[mf][1] = f2tf32(x1 - __uint_as_float(ahi[mf][1]));
                ahi[mf][2] = f2tf32(x2); alo[mf][2] = f2tf32(x2 - __uint_as_float(ahi[mf][2]));
                ahi[mf][3] = f2tf32(x3); alo[mf][3] = f2tf32(x3 - __uint_as_float(ahi[mf][3]));
            }
            unsigned bhi[4][2], blo[4][2];
#pragma unroll
            for (int nf = 0; nf < 4; nf++) {
                int n0 = wc * 32 + nf * 8 + qid;
                float y0 = Bs[kb + qtr][n0];
                float y1 = Bs[kb + qtr + 4][n0];
                bhi[nf][0] = f2tf32(y0); blo[nf][0] = f2tf32(y0 - __uint_as_float(bhi[nf][0]));
                bhi[nf][1] = f2tf32(y1); blo[nf][1] = f2tf32(y1 - __uint_as_float(bhi[nf][1]));
            }
#pragma unroll
            for (int mf = 0; mf < 4; mf++)
#pragma unroll
                for (int nf = 0; nf < 4; nf++) {
                    mma_tf32(acc[mf][nf], ahi[mf], bhi[nf]);
                    mma_tf32(acc[mf][nf], ahi[mf], blo[nf]);
                    mma_tf32(acc[mf][nf], alo[mf], bhi[nf]);
                }
        }
        __syncthreads();
    }

    // ---- epilogue: bias (+resid), write C ----
#pragma unroll
    for (int mf = 0; mf < 4; mf++) {
        int r0 = bm + wr * 64 + mf * 16 + qid;
#pragma unroll
        for (int nf = 0; nf < 4; nf++) {
            int c0 = wc * 32 + nf * 8 + qtr * 2;
            float2 bv = *(const float2*)&bias[c0];
            if (r0 < M) {
                float2 o;
                o.x = acc[mf][nf][0] + bv.x;
                o.y = acc[mf][nf][1] + bv.y;
                if (resid) {
                    float2 rv = *(const float2*)&resid[(size_t)r0 * 128 + c0];
                    o.x += rv.x; o.y += rv.y;
                }
                *(float2*)&C[(size_t)r0 * 128 + c0] = o;
            }
            if (r0 + 8 < M) {
                float2 o;
                o.x = acc[mf][nf][2] + bv.x;
                o.y = acc[mf][nf][3] + bv.y;
                if (resid) {
                    float2 rv = *(const float2*)&resid[(size_t)(r0 + 8) * 128 + c0];
                    o.x += rv.x; o.y += rv.y;
                }
                *(float2*)&C[(size_t)(r0 + 8) * 128 + c0] = o;
            }
        }
    }
}

// ---------------- zero kernel ------------------------------------------------
__global__ void zero_kernel(float4* __restrict__ p, int n4) {
    int i = blockIdx.x * blockDim.x + threadIdx.x;
    if (i < n4) p[i] = make_float4(0.f, 0.f, 0.f, 0.f);
}

// ---------------- edge pass: fused softmax num/denom via vector RED ---------
__global__ void edge_kernel(const float* __restrict__ h,
                            const int*   __restrict__ src,
                            const int*   __restrict__ dst,
                            float*       __restrict__ acc, int E) {
    int gw   = (blockIdx.x * blockDim.x + threadIdx.x) >> 5;
    int lane = threadIdx.x & 31;
    if (gw >= E) return;
    int s = __ldg(src + gw);
    int d = __ldg(dst + gw);
    float4 v = *(const float4*)&h[s * HH + lane * 4];
    float m0 = fmaxf(v.x, 0.f) + 1e-7f;
    float m1 = fmaxf(v.y, 0.f) + 1e-7f;
    float m2 = fmaxf(v.z, 0.f) + 1e-7f;
    float m3 = fmaxf(v.w, 0.f) + 1e-7f;
    float w0 = __expf(m0), w1 = __expf(m1), w2 = __expf(m2), w3 = __expf(m3);
    float* base = acc + d * (2 * HH) + lane * 8;
    asm volatile("red.global.add.v4.f32 [%0], {%1,%2,%3,%4};"
                 :: "l"(base), "f"(w0), "f"(m0 * w0), "f"(w1), "f"(m1 * w1) : "memory");
    asm volatile("red.global.add.v4.f32 [%0], {%1,%2,%3,%4};"
                 :: "l"(base + 4), "f"(w2), "f"(m2 * w2), "f"(w3), "f"(m3 * w3) : "memory");
}

// ---------------- LayerNorm + ReLU (warp per row) ---------------------------
__global__ void ln_relu_kernel(const float* __restrict__ in,
                               const float* __restrict__ g,
                               const float* __restrict__ b,
                               float* __restrict__ out, int M) {
    int gw   = (blockIdx.x * blockDim.x + threadIdx.x) >> 5;
    int lane = threadIdx.x & 31;
    if (gw >= M) return;
    float4 v = *(const float4*)&in[gw * HH + lane * 4];
    float s = v.x + v.y + v.z + v.w;
#pragma unroll
    for (int o = 16; o; o >>= 1) s += __shfl_xor_sync(0xffffffffu, s, o);
    float mu = s * (1.f / 128.f);
    float dx = v.x - mu, dy = v.y - mu, dz = v.z - mu, dw = v.w - mu;
    float q = dx * dx + dy * dy + dz * dz + dw * dw;
#pragma unroll
    for (int o = 16; o; o >>= 1) q += __shfl_xor_sync(0xffffffffu, q, o);
    float rs = rsqrtf(q * (1.f / 128.f) + 1e-5f);
    float4 gv = *(const float4*)&g[lane * 4];
    float4 bv = *(const float4*)&b[lane * 4];
    float4 o4;
    o4.x = fmaxf(dx * rs * gv.x + bv.x, 0.f);
    o4.y = fmaxf(dy * rs * gv.y + bv.y, 0.f);
    o4.z = fmaxf(dz * rs * gv.z + bv.z, 0.f);
    o4.w = fmaxf(dw * rs * gv.w + bv.w, 0.f);
    *(float4*)&out[gw * HH + lane * 4] = o4;
}

// ---------------- row gather out[n] = in[map[n]] ----------------------------
__global__ void gather_kernel(const float* __restrict__ in,
                              const int*   __restrict__ map,
                              float*       __restrict__ out, int M) {
    int i = blockIdx.x * blockDim.x + threadIdx.x;
    int n = i >> 5, f = i & 31;
    if (n >= M) return;
    int r = __ldg(map + n);
    ((float4*)out)[n * 32 + f] = ((const float4*)in)[r * 32 + f];
}

// ---------------- final: gather + LN + ReLU + pred GEMV + log_softmax -------
__global__ void final_kernel(const float* __restrict__ h,
                             const int*   __restrict__ fmap,
                             const float* __restrict__ g,
                             const float* __restrict__ b,
                             const float* __restrict__ pw,
                             const float* __restrict__ pb,
                             float* __restrict__ out) {
    __shared__ float sv[128];
    __shared__ float sl[CC];
    __shared__ float red[4];
    __shared__ float stats[2];
    int t = threadIdx.x;
    int lane = t & 31, warp = t >> 5;
    int row = __ldg(fmap + blockIdx.x);
    float x = h[row * HH + t];
    float s = x;
#pragma unroll
    for (int o = 16; o; o >>= 1) s += __shfl_xor_sync(0xffffffffu, s, o);
    if (lane == 0) red[warp] = s;
    __syncthreads();
    float mu = (red[0] + red[1] + red[2] + red[3]) * (1.f / 128.f);
    float d = x - mu;
    float q = d * d;
#pragma unroll
    for (int o = 16; o; o >>= 1) q += __shfl_xor_sync(0xffffffffu, q, o);
    __syncthreads();
    if (lane == 0) red[warp] = q;
    __syncthreads();
    float var = (red[0] + red[1] + red[2] + red[3]) * (1.f / 128.f);
    float rs = rsqrtf(var + 1e-5f);
    sv[t] = fmaxf(d * rs * g[t] + b[t], 0.f);
    __syncthreads();
    if (t < CC) {
        float a = pb[t];
#pragma unroll 8
        for (int k = 0; k < 128; k++) a += sv[k] * pw[k * CC + t];
        sl[t] = a;
    }
    __syncthreads();
    if (t == 0) {
        float mx = -1e30f;
        for (int c = 0; c < CC; c++) mx = fmaxf(mx, sl[c]);
        float se = 0.f;
        for (int c = 0; c < CC; c++) se += expf(sl[c] - mx);
        stats[0] = mx; stats[1] = logf(se);
    }
    __syncthreads();
    if (t < CC) out[blockIdx.x * CC + t] = sl[t] - stats[0] - stats[1];
}

// ---------------- host orchestration ----------------------------------------
extern "C" void kernel_launch(void* const* d_in, const int* in_sizes, int n_in,
                              void* d_out, int out_size) {
    const float* x        = (const float*)d_in[0];
    const int*   src      = (const int*)  d_in[1];
    const int*   dst      = (const int*)  d_in[2];
    const int*   node_map = (const int*)  d_in[3];
    const int*   fmap     = (const int*)  d_in[4];
    const float* enc_w    = (const float*)d_in[5];
    const float* enc_b    = (const float*)d_in[6];
    const float* gcn_w    = (const float*)d_in[7];
    const float* gcn_b    = (const float*)d_in[8];
    const float* ln_g     = (const float*)d_in[9];
    const float* ln_b     = (const float*)d_in[10];
    const float* pred_w   = (const float*)d_in[11];
    const float* pred_b   = (const float*)d_in[12];
    float* out = (float*)d_out;

    float *bA, *bB, *bC, *acc;
    cudaGetSymbolAddress((void**)&bA,  g_bufA);
    cudaGetSymbolAddress((void**)&bB,  g_bufB);
    cudaGetSymbolAddress((void**)&bC,  g_bufC);
    cudaGetSymbolAddress((void**)&acc, g_acc);

    const int gemmGrid = (NN + 127) / 128;
    const int accN4    = NN * HH * 2 / 4;
    const int zeroGrid = (accN4 + 255) / 256;
    const int edgeGrid = (EE * 32 + 255) / 256;
    const int rowGrid  = (NN * 32 + 255) / 256;

    // encoder: h = x @ enc_w + enc_b                       -> bA
    gemm_mma_kernel<0><<<gemmGrid, 256>>>(x, FINN, nullptr, enc_w, enc_b, nullptr, bA, NN);

    // conv0: h = (agg(bA)+bA) @ W0 + b0                    -> bB
    zero_kernel<<<zeroGrid, 256>>>((float4*)acc, accN4);
    edge_kernel<<<edgeGrid, 256>>>(bA, src, dst, acc, EE);
    gemm_mma_kernel<1><<<gemmGrid, 256>>>(bA, HH, acc, gcn_w, gcn_b, nullptr, bB, NN);

    // layer 1: h2 = relu(LN(bB)); h = conv(h2, edges0)+bB; h = h[node_map0]
    ln_relu_kernel<<<rowGrid, 256>>>(bB, ln_g, ln_b, bA, NN);
    zero_kernel<<<zeroGrid, 256>>>((float4*)acc, accN4);
    edge_kernel<<<edgeGrid, 256>>>(bA, src, dst, acc, EE);
    gemm_mma_kernel<1><<<gemmGrid, 256>>>(bA, HH, acc, gcn_w + HH * HH, gcn_b + HH, bB, bC, NN);
    gather_kernel<<<rowGrid, 256>>>(bC, node_map, bA, NN);

    // layer 2: h2 = relu(LN(bA)); h = conv(h2, edges1)+bA; h = h[node_map1]
    ln_relu_kernel<<<rowGrid, 256>>>(bA, ln_g + HH, ln_b + HH, bB, NN);
    zero_kernel<<<zeroGrid, 256>>>((float4*)acc, accN4);
    edge_kernel<<<edgeGrid, 256>>>(bB, src + EE, dst + EE, acc, EE);
    gemm_mma_kernel<1><<<gemmGrid, 256>>>(bB, HH, acc, gcn_w + 2 * HH * HH, gcn_b + 2 * HH, bA, bC, NN);
    gather_kernel<<<rowGrid, 256>>>(bC, node_map + NN, bB, NN);

    // final: LN+ReLU on the 10k seed rows only, pred linear, log_softmax
    final_kernel<<<NOUTT, 128>>>(bB, fmap, ln_g + 2 * HH, ln_b + 2 * HH, pred_w, pred_b, out);
}

// round 5
// speedup vs baseline: 1.4003x; 1.1653x over previous
#include <cuda_runtime.h>
#include <cuda_bf16.h>
#include <math.h>

#define NN   100000
#define EE   600000
#define FINN 256
#define HH   128
#define CC   47
#define NOUTT 10000

// ---------------- scratch (device globals; no allocations allowed) ----------
__device__ float g_bufA[(size_t)NN * HH];
__device__ float g_bufB[(size_t)NN * HH];
__device__ float g_bufC[(size_t)NN * HH];
__device__ float g_acc [(size_t)NN * HH * 2];   // interleaved {sum(w), sum(m*w)}

// ======================= TF32 mma helpers ===================================
__device__ __forceinline__ unsigned f2tf32(float x) {
    unsigned r;
    asm("cvt.rna.tf32.f32 %0, %1;" : "=r"(r) : "f"(x));
    return r;
}

__device__ __forceinline__ void mma_tf32(float* d, const unsigned* a, const unsigned* b) {
    asm volatile(
        "mma.sync.aligned.m16n8k8.row.col.f32.tf32.tf32.f32 "
        "{%0,%1,%2,%3}, {%4,%5,%6,%7}, {%8,%9}, {%0,%1,%2,%3};"
        : "+f"(d[0]), "+f"(d[1]), "+f"(d[2]), "+f"(d[3])
        : "r"(a[0]), "r"(a[1]), "r"(a[2]), "r"(a[3]), "r"(b[0]), "r"(b[1]));
}

// ---------------- TF32 split GEMM: C[M,128] = A'[M,K] @ W[K,128] + bias -----
// AMODE 0: A' = A (lda = K).  AMODE 1: A' = acc.mw/(acc.w+eps) + A (lda = 128).
// resid row index via rmap (identity if null). CTA: 256 thr, tile 128x128.
// SMEM holds pre-split tf32 hi/lo; inner loop is pure LDS + MMA.
#define APITCH 36
#define BPITCH 136
#define GSMEM_U (2 * 128 * APITCH + 2 * 32 * BPITCH)   // uints
#define GSMEM_B (GSMEM_U * 4)

template<int AMODE>
__global__ __launch_bounds__(256, 2) void gemm_mma_kernel(
    const float* __restrict__ A, int K,
    const float* __restrict__ accb,
    const float* __restrict__ W,
    const float* __restrict__ bias,
    const float* __restrict__ resid,
    const int*   __restrict__ rmap,
    float* __restrict__ C, int M)
{
    extern __shared__ unsigned smem_u[];
    unsigned* Ah = smem_u;                       // [128][APITCH]
    unsigned* Al = Ah + 128 * APITCH;
    unsigned* Bh = Al + 128 * APITCH;            // [32][BPITCH]
    unsigned* Bl = Bh + 32 * BPITCH;

    const int tid  = threadIdx.x;
    const int wid  = tid >> 5, lane = tid & 31;
    const int wr   = wid >> 2, wc = wid & 3;      // warp 2x4 grid
    const int qid  = lane >> 2, qtr = lane & 3;   // quad row / thread-in-quad
    const int bm   = blockIdx.x * 128;

    const int arow  = tid >> 1;
    const int apart = (tid & 1) * 16;
    const int agrow = bm + arow;
    const bool ain  = agrow < M;
    const int brow = tid >> 3;
    const int bcol = (tid & 7) * 16;

    float acc[4][4][4];
#pragma unroll
    for (int i = 0; i < 4; i++)
#pragma unroll
        for (int j = 0; j < 4; j++)
#pragma unroll
            for (int q = 0; q < 4; q++) acc[i][j][q] = 0.f;

    const int nchunks = K >> 5;
    for (int ch = 0; ch < nchunks; ch++) {
        const int k0 = ch * 32;
        // ---- load + split A tile ----
        {
            float v[16];
            if (ain) {
                if (AMODE == 0) {
                    const float4* ap = (const float4*)(A + (size_t)agrow * K + k0 + apart);
#pragma unroll
                    for (int j = 0; j < 4; j++) {
                        float4 t = ap[j];
                        v[j * 4 + 0] = t.x; v[j * 4 + 1] = t.y;
                        v[j * 4 + 2] = t.z; v[j * 4 + 3] = t.w;
                    }
                } else {
                    const float4* cp = (const float4*)(accb + (size_t)agrow * 256 + 2 * (k0 + apart));
                    const float4* ap = (const float4*)(A + (size_t)agrow * 128 + k0 + apart);
#pragma unroll
                    for (int j = 0; j < 8; j++) {
                        float4 t = cp[j];
                        v[j * 2 + 0] = t.y / (t.x + 1e-16f);
                        v[j * 2 + 1] = t.w / (t.z + 1e-16f);
                    }
#pragma unroll
                    for (int j = 0; j < 4; j++) {
                        float4 t = ap[j];
                        v[j * 4 + 0] += t.x; v[j * 4 + 1] += t.y;
                        v[j * 4 + 2] += t.z; v[j * 4 + 3] += t.w;
                    }
                }
            } else {
#pragma unroll
                for (int j = 0; j < 16; j++) v[j] = 0.f;
            }
            unsigned* dh = Ah + arow * APITCH + apart;
            unsigned* dl = Al + arow * APITCH + apart;
#pragma unroll
            for (int j = 0; j < 4; j++) {
                uint4 h4, l4;
                h4.x = f2tf32(v[j*4+0]); l4.x = f2tf32(v[j*4+0] - __uint_as_float(h4.x));
                h4.y = f2tf32(v[j*4+1]); l4.y = f2tf32(v[j*4+1] - __uint_as_float(h4.y));
                h4.z = f2tf32(v[j*4+2]); l4.z = f2tf32(v[j*4+2] - __uint_as_float(h4.z));
                h4.w = f2tf32(v[j*4+3]); l4.w = f2tf32(v[j*4+3] - __uint_as_float(h4.w));
                *(uint4*)(dh + j * 4) = h4;
                *(uint4*)(dl + j * 4) = l4;
            }
        }
        // ---- load + split B tile ----
        {
            const float4* wp = (const float4*)(W + (size_t)(k0 + brow) * 128 + bcol);
            unsigned* dh = Bh + brow * BPITCH + bcol;
            unsigned* dl = Bl + brow * BPITCH + bcol;
#pragma unroll
            for (int j = 0; j < 4; j++) {
                float4 t = wp[j];
                uint4 h4, l4;
                h4.x = f2tf32(t.x); l4.x = f2tf32(t.x - __uint_as_float(h4.x));
                h4.y = f2tf32(t.y); l4.y = f2tf32(t.y - __uint_as_float(h4.y));
                h4.z = f2tf32(t.z); l4.z = f2tf32(t.z - __uint_as_float(h4.z));
                h4.w = f2tf32(t.w); l4.w = f2tf32(t.w - __uint_as_float(h4.w));
                *(uint4*)(dh + j * 4) = h4;
                *(uint4*)(dl + j * 4) = l4;
            }
        }
        __syncthreads();

        // ---- 4 k-steps of 8 (pure LDS + MMA) ----
#pragma unroll
        for (int ks = 0; ks < 4; ks++) {
            const int kb = ks * 8;
            unsigned ahi[4][4], alo[4][4];
#pragma unroll
            for (int mf = 0; mf < 4; mf++) {
                int base = (wr * 64 + mf * 16 + qid) * APITCH + kb + qtr;
                ahi[mf][0] = Ah[base];
                ahi[mf][1] = Ah[base + 8 * APITCH];
                ahi[mf][2] = Ah[base + 4];
                ahi[mf][3] = Ah[base + 8 * APITCH + 4];
                alo[mf][0] = Al[base];
                alo[mf][1] = Al[base + 8 * APITCH];
                alo[mf][2] = Al[base + 4];
                alo[mf][3] = Al[base + 8 * APITCH + 4];
            }
            unsigned bhi[4][2], blo[4][2];
#pragma unroll
            for (int nf = 0; nf < 4; nf++) {
                int base = (kb + qtr) * BPITCH + wc * 32 + nf * 8 + qid;
                bhi[nf][0] = Bh[base];
                bhi[nf][1] = Bh[base + 4 * BPITCH];
                blo[nf][0] = Bl[base];
                blo[nf][1] = Bl[base + 4 * BPITCH];
            }
#pragma unroll
            for (int mf = 0; mf < 4; mf++)
#pragma unroll
                for (int nf = 0; nf < 4; nf++) {
                    mma_tf32(acc[mf][nf], ahi[mf], bhi[nf]);
                    mma_tf32(acc[mf][nf], ahi[mf], blo[nf]);
                    mma_tf32(acc[mf][nf], alo[mf], bhi[nf]);
                }
        }
        __syncthreads();
    }

    // ---- epilogue: bias (+resid via rmap), write C ----
#pragma unroll
    for (int mf = 0; mf < 4; mf++) {
        int r0 = bm + wr * 64 + mf * 16 + qid;
        int rr0 = 0, rr1 = 0;
        if (resid) {
            if (r0 < M)     rr0 = rmap ? __ldg(rmap + r0)     : r0;
            if (r0 + 8 < M) rr1 = rmap ? __ldg(rmap + r0 + 8) : r0 + 8;
        }
#pragma unroll
        for (int nf = 0; nf < 4; nf++) {
            int c0 = wc * 32 + nf * 8 + qtr * 2;
            float2 bv = *(const float2*)&bias[c0];
            if (r0 < M) {
                float2 o;
                o.x = acc[mf][nf][0] + bv.x;
                o.y = acc[mf][nf][1] + bv.y;
                if (resid) {
                    float2 rv = *(const float2*)&resid[(size_t)rr0 * 128 + c0];
                    o.x += rv.x; o.y += rv.y;
                }
                *(float2*)&C[(size_t)r0 * 128 + c0] = o;
            }
            if (r0 + 8 < M) {
                float2 o;
                o.x = acc[mf][nf][2] + bv.x;
                o.y = acc[mf][nf][3] + bv.y;
                if (resid) {
                    float2 rv = *(const float2*)&resid[(size_t)rr1 * 128 + c0];
                    o.x += rv.x; o.y += rv.y;
                }
                *(float2*)&C[(size_t)(r0 + 8) * 128 + c0] = o;
            }
        }
    }
}

// ---------------- zero kernel ------------------------------------------------
__global__ void zero_kernel(float4* __restrict__ p, int n4) {
    int i = blockIdx.x * blockDim.x + threadIdx.x;
    if (i < n4) p[i] = make_float4(0.f, 0.f, 0.f, 0.f);
}

// ---------------- edge pass: fused softmax num/denom via vector RED ---------
__global__ void edge_kernel(const float* __restrict__ h,
                            const int*   __restrict__ src,
                            const int*   __restrict__ dst,
                            float*       __restrict__ acc, int E) {
    int gw   = (blockIdx.x * blockDim.x + threadIdx.x) >> 5;
    int lane = threadIdx.x & 31;
    if (gw >= E) return;
    int s = __ldg(src + gw);
    int d = __ldg(dst + gw);
    float4 v = *(const float4*)&h[s * HH + lane * 4];
    float m0 = fmaxf(v.x, 0.f) + 1e-7f;
    float m1 = fmaxf(v.y, 0.f) + 1e-7f;
    float m2 = fmaxf(v.z, 0.f) + 1e-7f;
    float m3 = fmaxf(v.w, 0.f) + 1e-7f;
    float w0 = __expf(m0), w1 = __expf(m1), w2 = __expf(m2), w3 = __expf(m3);
    float* base = acc + d * (2 * HH) + lane * 8;
    asm volatile("red.global.add.v4.f32 [%0], {%1,%2,%3,%4};"
                 :: "l"(base), "f"(w0), "f"(m0 * w0), "f"(w1), "f"(m1 * w1) : "memory");
    asm volatile("red.global.add.v4.f32 [%0], {%1,%2,%3,%4};"
                 :: "l"(base + 4), "f"(w2), "f"(m2 * w2), "f"(w3), "f"(m3 * w3) : "memory");
}

// ---------------- LayerNorm + ReLU (warp per row, optional input gather) ----
__global__ void ln_relu_kernel(const float* __restrict__ in,
                               const int*   __restrict__ map,
                               const float* __restrict__ g,
                               const float* __restrict__ b,
                               float* __restrict__ out, int M) {
    int gw   = (blockIdx.x * blockDim.x + threadIdx.x) >> 5;
    int lane = threadIdx.x & 31;
    if (gw >= M) return;
    int srow = map ? __ldg(map + gw) : gw;
    float4 v = *(const float4*)&in[(size_t)srow * HH + lane * 4];
    float s = v.x + v.y + v.z + v.w;
#pragma unroll
    for (int o = 16; o; o >>= 1) s += __shfl_xor_sync(0xffffffffu, s, o);
    float mu = s * (1.f / 128.f);
    float dx = v.x - mu, dy = v.y - mu, dz = v.z - mu, dw = v.w - mu;
    float q = dx * dx + dy * dy + dz * dz + dw * dw;
#pragma unroll
    for (int o = 16; o; o >>= 1) q += __shfl_xor_sync(0xffffffffu, q, o);
    float rs = rsqrtf(q * (1.f / 128.f) + 1e-5f);
    float4 gv = *(const float4*)&g[lane * 4];
    float4 bv = *(const float4*)&b[lane * 4];
    float4 o4;
    o4.x = fmaxf(dx * rs * gv.x + bv.x, 0.f);
    o4.y = fmaxf(dy * rs * gv.y + bv.y, 0.f);
    o4.z = fmaxf(dz * rs * gv.z + bv.z, 0.f);
    o4.w = fmaxf(dw * rs * gv.w + bv.w, 0.f);
    *(float4*)&out[gw * HH + lane * 4] = o4;
}

// ---------------- final: composed gather + LN + ReLU + pred + log_softmax --
__global__ void final_kernel(const float* __restrict__ h,
                             const int*   __restrict__ nmap,
                             const int*   __restrict__ fmap,
                             const float* __restrict__ g,
                             const float* __restrict__ b,
                             const float* __restrict__ pw,
                             const float* __restrict__ pb,
                             float* __restrict__ out) {
    __shared__ float sv[128];
    __shared__ float sl[CC];
    __shared__ float red[4];
    __shared__ float stats[2];
    int t = threadIdx.x;
    int lane = t & 31, warp = t >> 5;
    int row = __ldg(nmap + __ldg(fmap + blockIdx.x));
    float x = h[(size_t)row * HH + t];
    float s = x;
#pragma unroll
    for (int o = 16; o; o >>= 1) s += __shfl_xor_sync(0xffffffffu, s, o);
    if (lane == 0) red[warp] = s;
    __syncthreads();
    float mu = (red[0] + red[1] + red[2] + red[3]) * (1.f / 128.f);
    float d = x - mu;
    float q = d * d;
#pragma unroll
    for (int o = 16; o; o >>= 1) q += __shfl_xor_sync(0xffffffffu, q, o);
    __syncthreads();
    if (lane == 0) red[warp] = q;
    __syncthreads();
    float var = (red[0] + red[1] + red[2] + red[3]) * (1.f / 128.f);
    float rs = rsqrtf(var + 1e-5f);
    sv[t] = fmaxf(d * rs * g[t] + b[t], 0.f);
    __syncthreads();
    if (t < CC) {
        float a = pb[t];
#pragma unroll 8
        for (int k = 0; k < 128; k++) a += sv[k] * pw[k * CC + t];
        sl[t] = a;
    }
    __syncthreads();
    if (t == 0) {
        float mx = -1e30f;
        for (int c = 0; c < CC; c++) mx = fmaxf(mx, sl[c]);
        float se = 0.f;
        for (int c = 0; c < CC; c++) se += expf(sl[c] - mx);
        stats[0] = mx; stats[1] = logf(se);
    }
    __syncthreads();
    if (t < CC) out[blockIdx.x * CC + t] = sl[t] - stats[0] - stats[1];
}

// ---------------- host orchestration ----------------------------------------
extern "C" void kernel_launch(void* const* d_in, const int* in_sizes, int n_in,
                              void* d_out, int out_size) {
    const float* x        = (const float*)d_in[0];
    const int*   src      = (const int*)  d_in[1];
    const int*   dst      = (const int*)  d_in[2];
    const int*   node_map = (const int*)  d_in[3];
    const int*   fmap     = (const int*)  d_in[4];
    const float* enc_w    = (const float*)d_in[5];
    const float* enc_b    = (const float*)d_in[6];
    const float* gcn_w    = (const float*)d_in[7];
    const float* gcn_b    = (const float*)d_in[8];
    const float* ln_g     = (const float*)d_in[9];
    const float* ln_b     = (const float*)d_in[10];
    const float* pred_w   = (const float*)d_in[11];
    const float* pred_b   = (const float*)d_in[12];
    float* out = (float*)d_out;

    float *bA, *bB, *bC, *acc;
    cudaGetSymbolAddress((void**)&bA,  g_bufA);
    cudaGetSymbolAddress((void**)&bB,  g_bufB);
    cudaGetSymbolAddress((void**)&bC,  g_bufC);
    cudaGetSymbolAddress((void**)&acc, g_acc);

    cudaFuncSetAttribute(gemm_mma_kernel<0>, cudaFuncAttributeMaxDynamicSharedMemorySize, GSMEM_B);
    cudaFuncSetAttribute(gemm_mma_kernel<1>, cudaFuncAttributeMaxDynamicSharedMemorySize, GSMEM_B);

    const int gemmGrid = (NN + 127) / 128;
    const int accN4    = NN * HH * 2 / 4;
    const int zeroGrid = (accN4 + 255) / 256;
    const int edgeGrid = (EE * 32 + 255) / 256;
    const int rowGrid  = (NN * 32 + 255) / 256;

    // encoder: h = x @ enc_w + enc_b                       -> bA
    gemm_mma_kernel<0><<<gemmGrid, 256, GSMEM_B>>>(x, FINN, nullptr, enc_w, enc_b,
                                                   nullptr, nullptr, bA, NN);

    // conv0: h = (agg(bA)+bA) @ W0 + b0                    -> bB
    zero_kernel<<<zeroGrid, 256>>>((float4*)acc, accN4);
    edge_kernel<<<edgeGrid, 256>>>(bA, src, dst, acc, EE);
    gemm_mma_kernel<1><<<gemmGrid, 256, GSMEM_B>>>(bA, HH, acc, gcn_w, gcn_b,
                                                   nullptr, nullptr, bB, NN);

    // layer 1: h2 = relu(LN(bB)) -> bA; h = conv(h2,e0)+bB -> bC  (gather deferred)
    ln_relu_kernel<<<rowGrid, 256>>>(bB, nullptr, ln_g, ln_b, bA, NN);
    zero_kernel<<<zeroGrid, 256>>>((float4*)acc, accN4);
    edge_kernel<<<edgeGrid, 256>>>(bA, src, dst, acc, EE);
    gemm_mma_kernel<1><<<gemmGrid, 256, GSMEM_B>>>(bA, HH, acc, gcn_w + HH * HH, gcn_b + HH,
                                                   bB, nullptr, bC, NN);

    // layer 2: h = bC[node_map0] (fused): h2 = relu(LN(h)) -> bB;
    //          h = conv(h2,e1) + bC[node_map0]             -> bA
    ln_relu_kernel<<<rowGrid, 256>>>(bC, node_map, ln_g + HH, ln_b + HH, bB, NN);
    zero_kernel<<<zeroGrid, 256>>>((float4*)acc, accN4);
    edge_kernel<<<edgeGrid, 256>>>(bB, src + EE, dst + EE, acc, EE);
    gemm_mma_kernel<1><<<gemmGrid, 256, GSMEM_B>>>(bB, HH, acc, gcn_w + 2 * HH * HH,
                                                   gcn_b + 2 * HH, bC, node_map, bA, NN);

    // final: rows bA[node_map1[fmap[b]]]; LN+ReLU+pred+log_softmax
    final_kernel<<<NOUTT, 128>>>(bA, node_map + NN, fmap, ln_g + 2 * HH, ln_b + 2 * HH,
                                 pred_w, pred_b, out);
}